// round 1
// baseline (speedup 1.0000x reference)
#include <cuda_runtime.h>

#define NN 8192
#define IN_DIM 256
#define HID 128
#define SMP 129   // smem pitch (pad to kill bank conflicts)

// Scratch (no cudaMalloc allowed)
__device__ float g_Z[NN * HID];
__device__ float g_rowsum[NN];

// ---------------------------------------------------------------------------
// Zero-init: out region of d_out + rowsum accumulator (must run every call)
// ---------------------------------------------------------------------------
__global__ void k_zero(float* __restrict__ out) {
    int i = blockIdx.x * blockDim.x + threadIdx.x;
    if (i < NN * HID) out[i] = 0.0f;
    if (i < NN) g_rowsum[i] = 0.0f;
}

// ---------------------------------------------------------------------------
// Phase 1: Z[n,h] = sum_k X[n,k] * W[h,k]   (both K-major, NT GEMM)
// Tile 64x64, 256 threads, 4x4 per thread, K-step 32.
// ---------------------------------------------------------------------------
__global__ __launch_bounds__(256) void k_gemm_z(const float* __restrict__ X,
                                                const float* __restrict__ W) {
    __shared__ float Xs[64][33];
    __shared__ float Ws[64][33];
    const int tid = threadIdx.x;
    const int tx = tid & 15, ty = tid >> 4;
    const int row0 = blockIdx.x * 64;
    const int col0 = blockIdx.y * 64;
    float acc[4][4] = {};

    for (int k0 = 0; k0 < IN_DIM; k0 += 32) {
        for (int idx = tid; idx < 64 * 32; idx += 256) {
            int r = idx >> 5, c = idx & 31;
            Xs[r][c] = X[(row0 + r) * IN_DIM + k0 + c];
            Ws[r][c] = W[(col0 + r) * IN_DIM + k0 + c];
        }
        __syncthreads();
        #pragma unroll 8
        for (int k = 0; k < 32; k++) {
            float a[4], b[4];
            #pragma unroll
            for (int i = 0; i < 4; i++) a[i] = Xs[ty * 4 + i][k];
            #pragma unroll
            for (int j = 0; j < 4; j++) b[j] = Ws[tx * 4 + j][k];
            #pragma unroll
            for (int i = 0; i < 4; i++)
                #pragma unroll
                for (int j = 0; j < 4; j++) acc[i][j] = fmaf(a[i], b[j], acc[i][j]);
        }
        __syncthreads();
    }
    #pragma unroll
    for (int i = 0; i < 4; i++)
        #pragma unroll
        for (int j = 0; j < 4; j++)
            g_Z[(row0 + ty * 4 + i) * HID + col0 + tx * 4 + j] = acc[i][j];
}

// ---------------------------------------------------------------------------
// Phase 2: for each 128-row block of A (grid.y) and each column split (grid.x):
//   loop over 16 column tiles of 128:
//     S = relu(Zn @ Zm^T)  -> write unnormalized to A, accumulate rowsum
//     out_unnorm += S @ Zm (kept in registers across the tile loop)
// smem: Zn(66KB) + Zm(66KB) + Ss(66KB) = 198KB dynamic.
// ---------------------------------------------------------------------------
__global__ __launch_bounds__(256, 1) void k_pass2(float* __restrict__ A,
                                                  float* __restrict__ out_acc) {
    extern __shared__ float sm[];
    float* Zn = sm;
    float* Zm = sm + 128 * SMP;
    float* Ss = sm + 2 * 128 * SMP;
    __shared__ float rs_loc[128];

    const int tid = threadIdx.x;
    const int tx = tid & 15, ty = tid >> 4;
    const int rb = ty * 8, cb = tx * 8;
    const int n0 = blockIdx.y * 128;

    // Load Zn (persistent for this CTA)
    for (int idx = tid; idx < 128 * 128; idx += 256) {
        int r = idx >> 7, c = idx & 127;
        Zn[r * SMP + c] = g_Z[(n0 + r) * HID + c];
    }
    if (tid < 128) rs_loc[tid] = 0.0f;

    float oacc[8][8] = {};

    for (int t = 0; t < 16; t++) {
        const int m0 = (blockIdx.x * 16 + t) * 128;
        __syncthreads();  // prior iteration done with Zm/Ss
        for (int idx = tid; idx < 128 * 128; idx += 256) {
            int r = idx >> 7, c = idx & 127;
            Zm[r * SMP + c] = g_Z[(m0 + r) * HID + c];
        }
        __syncthreads();

        // GEMM1: S[r,c] = sum_h Zn[r,h] * Zm[c,h]
        float acc[8][8] = {};
        for (int k = 0; k < 128; k++) {
            float a[8], b[8];
            #pragma unroll
            for (int i = 0; i < 8; i++) a[i] = Zn[(rb + i) * SMP + k];
            #pragma unroll
            for (int j = 0; j < 8; j++) b[j] = Zm[(cb + j) * SMP + k];
            #pragma unroll
            for (int i = 0; i < 8; i++)
                #pragma unroll
                for (int j = 0; j < 8; j++) acc[i][j] = fmaf(a[i], b[j], acc[i][j]);
        }

        // ReLU, stage to Ss, rowsum partial, write unnormalized A (float4)
        #pragma unroll
        for (int i = 0; i < 8; i++) {
            float rsum = 0.0f;
            #pragma unroll
            for (int jj = 0; jj < 8; jj += 4) {
                float v0 = fmaxf(acc[i][jj + 0], 0.0f);
                float v1 = fmaxf(acc[i][jj + 1], 0.0f);
                float v2 = fmaxf(acc[i][jj + 2], 0.0f);
                float v3 = fmaxf(acc[i][jj + 3], 0.0f);
                float* srow = &Ss[(rb + i) * SMP + cb + jj];
                srow[0] = v0; srow[1] = v1; srow[2] = v2; srow[3] = v3;
                rsum += (v0 + v1) + (v2 + v3);
                *(float4*)&A[(long)(n0 + rb + i) * NN + m0 + cb + jj] =
                    make_float4(v0, v1, v2, v3);
            }
            atomicAdd(&rs_loc[rb + i], rsum);
        }
        __syncthreads();

        // GEMM2: out[r,h] += sum_m Ss[r,m] * Zm[m,h]
        for (int m = 0; m < 128; m++) {
            float a[8], b[8];
            #pragma unroll
            for (int i = 0; i < 8; i++) a[i] = Ss[(rb + i) * SMP + m];
            #pragma unroll
            for (int j = 0; j < 8; j++) b[j] = Zm[m * SMP + cb + j];
            #pragma unroll
            for (int i = 0; i < 8; i++)
                #pragma unroll
                for (int j = 0; j < 8; j++) oacc[i][j] = fmaf(a[i], b[j], oacc[i][j]);
        }
    }

    __syncthreads();
    if (tid < 128) atomicAdd(&g_rowsum[n0 + tid], rs_loc[tid]);
    #pragma unroll
    for (int i = 0; i < 8; i++)
        #pragma unroll
        for (int j = 0; j < 8; j++)
            atomicAdd(&out_acc[(n0 + rb + i) * HID + cb + j], oacc[i][j]);
}

// ---------------------------------------------------------------------------
// Phase 3a: A[n,:] *= 1/(rowsum[n] + 1e-6)  (float4 grid-stride)
// ---------------------------------------------------------------------------
__global__ void k_norm_A(float* __restrict__ A) {
    long i = (long)blockIdx.x * blockDim.x + threadIdx.x;  // float4 index
    const long total = (long)NN * NN / 4;
    if (i < total) {
        int r = (int)(i >> 11);  // 2048 float4 per row
        float inv = 1.0f / (g_rowsum[r] + 1e-6f);
        float4 v = ((float4*)A)[i];
        v.x *= inv; v.y *= inv; v.z *= inv; v.w *= inv;
        ((float4*)A)[i] = v;
    }
}

// ---------------------------------------------------------------------------
// Phase 3b: out[n,:] *= 1/(rowsum[n] + 1e-6)
// ---------------------------------------------------------------------------
__global__ void k_norm_out(float* __restrict__ o) {
    int i = blockIdx.x * blockDim.x + threadIdx.x;
    if (i < NN * HID) {
        int r = i >> 7;
        o[i] *= 1.0f / (g_rowsum[r] + 1e-6f);
    }
}

// ---------------------------------------------------------------------------
extern "C" void kernel_launch(void* const* d_in, const int* in_sizes, int n_in,
                              void* d_out, int out_size) {
    const float* X = (const float*)d_in[0];  // [8192, 256]
    const float* W = (const float*)d_in[1];  // [128, 256]
    float* out = (float*)d_out;              // first 8192*128 floats
    float* A = out + NN * HID;               // then 8192*8192 floats

    k_zero<<<(NN * HID + 255) / 256, 256>>>(out);
    k_gemm_z<<<dim3(NN / 64, HID / 64), 256>>>(X, W);

    static const size_t smem = 3 * 128 * SMP * sizeof(float);  // 198144 B
    cudaFuncSetAttribute(k_pass2, cudaFuncAttributeMaxDynamicSharedMemorySize,
                         (int)smem);
    k_pass2<<<dim3(4, NN / 128), 256, smem>>>(A, out);

    k_norm_A<<<(int)(((long)NN * NN / 4 + 255) / 256), 256>>>(A);
    k_norm_out<<<(NN * HID + 255) / 256, 256>>>(out);
}

// round 3
// speedup vs baseline: 3.4005x; 3.4005x over previous
#include <cuda_runtime.h>
#include <cuda_bf16.h>
#include <cstdint>

#define NN 8192
#define IN_DIM 256
#define HID 128
#define P 136  // smem pitch in bf16 elems (272B: odd 16B stride -> ldmatrix conflict-free)

// tile offsets in bf16 elems within dynamic smem
#define ZNH 0
#define ZNL (128 * P)
#define ZTH (2 * 128 * P)
#define ZTL (3 * 128 * P)
#define SHI (4 * 128 * P)
#define SLO (5 * 128 * P)
#define SMEM_BYTES (6 * 128 * P * 2)  // 208896

// ---------------- device scratch (no cudaMalloc allowed) -------------------
__device__ __nv_bfloat16 g_Zhi[NN * HID];
__device__ __nv_bfloat16 g_Zlo[NN * HID];
__device__ __nv_bfloat16 g_ZThi[(long)HID * NN];
__device__ __nv_bfloat16 g_ZTlo[(long)HID * NN];
__device__ float g_rowsum[NN];

// ---------------- warp-MMA primitives (baseline PTX, no sm_103a gating) ----
__device__ __forceinline__ uint32_t smem_u32(const void* p) {
    uint32_t a;
    asm("{ .reg .u64 t; cvta.to.shared.u64 t, %1; cvt.u32.u64 %0, t; }"
        : "=r"(a) : "l"(p));
    return a;
}
__device__ __forceinline__ void ldsm_x4(uint32_t* r, uint32_t addr) {
    asm volatile("ldmatrix.sync.aligned.m8n8.x4.shared.b16 {%0,%1,%2,%3}, [%4];"
                 : "=r"(r[0]), "=r"(r[1]), "=r"(r[2]), "=r"(r[3]) : "r"(addr));
}
__device__ __forceinline__ void ldsm_x2t(uint32_t* r, uint32_t addr) {
    asm volatile("ldmatrix.sync.aligned.m8n8.x2.trans.shared.b16 {%0,%1}, [%2];"
                 : "=r"(r[0]), "=r"(r[1]) : "r"(addr));
}
__device__ __forceinline__ void ldsm_x2(uint32_t* r, uint32_t addr) {
    asm volatile("ldmatrix.sync.aligned.m8n8.x2.shared.b16 {%0,%1}, [%2];"
                 : "=r"(r[0]), "=r"(r[1]) : "r"(addr));
}
__device__ __forceinline__ void mma16816(float* c, const uint32_t* a,
                                         const uint32_t* b) {
    asm volatile(
        "mma.sync.aligned.m16n8k16.row.col.f32.bf16.bf16.f32 "
        "{%0,%1,%2,%3}, {%4,%5,%6,%7}, {%8,%9}, {%0,%1,%2,%3};"
        : "+f"(c[0]), "+f"(c[1]), "+f"(c[2]), "+f"(c[3])
        : "r"(a[0]), "r"(a[1]), "r"(a[2]), "r"(a[3]), "r"(b[0]), "r"(b[1]));
}
__device__ __forceinline__ uint32_t pack_bf2(float x, float y) {
    __nv_bfloat162 t;
    t.x = __float2bfloat16(x);
    t.y = __float2bfloat16(y);
    return *reinterpret_cast<uint32_t*>(&t);
}

// ---------------------------------------------------------------------------
__global__ void k_zero(float* __restrict__ out) {
    int i = blockIdx.x * blockDim.x + threadIdx.x;
    if (i < NN * HID) out[i] = 0.0f;
    if (i < NN) g_rowsum[i] = 0.0f;
}

// ---------------------------------------------------------------------------
// Phase 1: Z = X @ W^T (fp32), emit bf16 hi/lo + transposed hi/lo
// ---------------------------------------------------------------------------
__global__ __launch_bounds__(256) void k_gemm_z(const float* __restrict__ X,
                                                const float* __restrict__ W) {
    __shared__ float Xs[64][33];
    __shared__ float Ws[64][33];
    const int tid = threadIdx.x;
    const int tx = tid & 15, ty = tid >> 4;
    const int row0 = blockIdx.x * 64;
    const int col0 = blockIdx.y * 64;
    float acc[4][4] = {};

    for (int k0 = 0; k0 < IN_DIM; k0 += 32) {
        for (int idx = tid; idx < 64 * 32; idx += 256) {
            int r = idx >> 5, c = idx & 31;
            Xs[r][c] = X[(row0 + r) * IN_DIM + k0 + c];
            Ws[r][c] = W[(col0 + r) * IN_DIM + k0 + c];
        }
        __syncthreads();
#pragma unroll 8
        for (int k = 0; k < 32; k++) {
            float a[4], b[4];
#pragma unroll
            for (int i = 0; i < 4; i++) a[i] = Xs[ty * 4 + i][k];
#pragma unroll
            for (int j = 0; j < 4; j++) b[j] = Ws[tx * 4 + j][k];
#pragma unroll
            for (int i = 0; i < 4; i++)
#pragma unroll
                for (int j = 0; j < 4; j++) acc[i][j] = fmaf(a[i], b[j], acc[i][j]);
        }
        __syncthreads();
    }
#pragma unroll
    for (int i = 0; i < 4; i++)
#pragma unroll
        for (int j = 0; j < 4; j++) {
            int r = row0 + ty * 4 + i, c = col0 + tx * 4 + j;
            float v = acc[i][j];
            __nv_bfloat16 h = __float2bfloat16(v);
            __nv_bfloat16 l = __float2bfloat16(v - __bfloat162float(h));
            g_Zhi[r * HID + c] = h;
            g_Zlo[r * HID + c] = l;
            g_ZThi[(long)c * NN + r] = h;
            g_ZTlo[(long)c * NN + r] = l;
        }
}

// ---------------------------------------------------------------------------
// copy 128x128 bf16 tile (global row-major, stride) -> smem pitched tile
// ---------------------------------------------------------------------------
__device__ __forceinline__ void copy_tile(__nv_bfloat16* __restrict__ dst,
                                          const __nv_bfloat16* __restrict__ src,
                                          long stride, int tid) {
#pragma unroll
    for (int i = 0; i < 8; i++) {
        int idx = tid + i * 256;
        int row = idx >> 4;
        int c8 = (idx & 15) * 8;
        *(uint4*)&dst[row * P + c8] = *(const uint4*)&src[(long)row * stride + c8];
    }
}

// ---------------------------------------------------------------------------
// Phase 2 (HMMA): CTA = 128-row block x half the column tiles.
// GEMM1 (split-bf16 x3): S = relu(Zn @ Zm^T); epilogue writes unnormalized A,
// rowsum (regs), S->smem bf16 hi/lo; GEMM2 (split-bf16 x3): out += S @ Zm.
// Warp grid 2(m) x 4(n); warp tile 64x32; out accum in regs across all tiles.
// ---------------------------------------------------------------------------
__global__ __launch_bounds__(256, 1) void k_pass2(float* __restrict__ A,
                                                  float* __restrict__ out) {
    extern __shared__ __nv_bfloat16 sm[];
    const uint32_t smb = smem_u32(sm);
    const int tid = threadIdx.x;
    const int wid = tid >> 5, lane = tid & 31;
    const int wm = wid & 1, wn = wid >> 1;
    const int g = lane >> 2, tq = lane & 3;
    const int n0 = blockIdx.y * 128;
    const int cs = blockIdx.x;

    copy_tile(sm + ZNH, g_Zhi + (long)n0 * HID, HID, tid);
    copy_tile(sm + ZNL, g_Zlo + (long)n0 * HID, HID, tid);

    // ldmatrix address components (bytes)
    const int l15 = lane & 15;
    const int aRow = wm * 64 + l15;               // GEMM1/2 A row (x4)
    const int aColOff = (lane >> 4) * 8;          // k-half select (x4)
    const uint32_t a1base = smb + (ZNH + aRow * P + aColOff) * 2;
    const uint32_t a1lo = smb + (ZNL + aRow * P + aColOff) * 2;
    const uint32_t aSbase = smb + (SHI + aRow * P + aColOff) * 2;
    const uint32_t aSlo = smb + (SLO + aRow * P + aColOff) * 2;
    // GEMM1 B (x2.trans): rows = k (h), col = warp n-slice
    const uint32_t b1base = smb + (ZTH + l15 * P + wn * 32) * 2;
    const uint32_t b1lo = smb + (ZTL + l15 * P + wn * 32) * 2;
    // GEMM2 B (x2): rows = n (h), col = k-half
    const int b2row = wn * 32 + (lane & 7);
    const int b2off = ((lane >> 3) & 1) * 8;
    const uint32_t b2base = smb + (ZTH + b2row * P + b2off) * 2;
    const uint32_t b2lo = smb + (ZTL + b2row * P + b2off) * 2;

    float oacc[4][4][4] = {};
    float rs[4][2] = {};

    for (int t = 0; t < 32; t++) {
        const int m0 = (cs * 32 + t) * 128;
        __syncthreads();  // prev GEMM2 done with Zt/S
        copy_tile(sm + ZTH, g_ZThi + m0, NN, tid);
        copy_tile(sm + ZTL, g_ZTlo + m0, NN, tid);
        __syncthreads();

        // ---- GEMM1: cacc = Zn (split) @ Zt (split) ----
        float cacc[4][4][4] = {};
#pragma unroll
        for (int p = 0; p < 3; p++) {
            const uint32_t aB = (p == 2) ? a1lo : a1base;
            const uint32_t bB = (p == 1) ? b1lo : b1base;
#pragma unroll
            for (int k8 = 0; k8 < 8; k8++) {
                const int k0 = k8 * 16;
                uint32_t a[4][4];
#pragma unroll
                for (int mf = 0; mf < 4; mf++)
                    ldsm_x4(a[mf], aB + (mf * 16 * P + k0) * 2);
#pragma unroll
                for (int nf = 0; nf < 4; nf++) {
                    uint32_t b[2];
                    ldsm_x2t(b, bB + (k0 * P + nf * 8) * 2);
#pragma unroll
                    for (int mf = 0; mf < 4; mf++)
                        mma16816(cacc[mf][nf], a[mf], b);
                }
            }
        }

        // ---- epilogue: relu, rowsum, A write, S -> smem hi/lo ----
#pragma unroll
        for (int mf = 0; mf < 4; mf++) {
#pragma unroll
            for (int nf = 0; nf < 4; nf++) {
                float* c = cacc[mf][nf];
                float v0 = fmaxf(c[0], 0.f), v1 = fmaxf(c[1], 0.f);
                float v2 = fmaxf(c[2], 0.f), v3 = fmaxf(c[3], 0.f);
                rs[mf][0] += v0 + v1;
                rs[mf][1] += v2 + v3;
                const int lr = wm * 64 + mf * 16 + g;
                const int lc = wn * 32 + nf * 8 + 2 * tq;
                const long gr0 = (long)(n0 + lr) * NN + m0 + lc;
                const long gr1 = gr0 + 8L * NN;
                *(float2*)&A[gr0] = make_float2(v0, v1);
                *(float2*)&A[gr1] = make_float2(v2, v3);
                float h0 = __bfloat162float(__float2bfloat16(v0));
                float h1 = __bfloat162float(__float2bfloat16(v1));
                float h2 = __bfloat162float(__float2bfloat16(v2));
                float h3 = __bfloat162float(__float2bfloat16(v3));
                *(uint32_t*)&sm[SHI + lr * P + lc] = pack_bf2(v0, v1);
                *(uint32_t*)&sm[SLO + lr * P + lc] = pack_bf2(v0 - h0, v1 - h1);
                *(uint32_t*)&sm[SHI + (lr + 8) * P + lc] = pack_bf2(v2, v3);
                *(uint32_t*)&sm[SLO + (lr + 8) * P + lc] = pack_bf2(v2 - h2, v3 - h3);
            }
        }
        __syncthreads();

        // ---- GEMM2: oacc += S (split) @ Zt-as-B (split) ----
#pragma unroll
        for (int p = 0; p < 3; p++) {
            const uint32_t aB = (p == 2) ? aSlo : aSbase;
            const uint32_t bB = (p == 1) ? b2lo : b2base;
#pragma unroll
            for (int k8 = 0; k8 < 8; k8++) {
                const int k0 = k8 * 16;
                uint32_t a[4][4];
#pragma unroll
                for (int mf = 0; mf < 4; mf++)
                    ldsm_x4(a[mf], aB + (mf * 16 * P + k0) * 2);
#pragma unroll
                for (int nf = 0; nf < 4; nf++) {
                    uint32_t b[2];
                    ldsm_x2(b, bB + (nf * 8 * P + k0) * 2);
#pragma unroll
                    for (int mf = 0; mf < 4; mf++)
                        mma16816(oacc[mf][nf], a[mf], b);
                }
            }
        }
    }

    // ---- rowsum reduce (quad shuffle) + atomics ----
#pragma unroll
    for (int mf = 0; mf < 4; mf++)
#pragma unroll
        for (int h = 0; h < 2; h++) {
            float v = rs[mf][h];
            v += __shfl_xor_sync(0xFFFFFFFFu, v, 1);
            v += __shfl_xor_sync(0xFFFFFFFFu, v, 2);
            if (tq == 0)
                atomicAdd(&g_rowsum[n0 + wm * 64 + mf * 16 + g + 8 * h], v);
        }

    // ---- out accumulate ----
#pragma unroll
    for (int mf = 0; mf < 4; mf++)
#pragma unroll
        for (int nf = 0; nf < 4; nf++) {
            const int r0 = n0 + wm * 64 + mf * 16 + g;
            const int col = wn * 32 + nf * 8 + 2 * tq;
            atomicAdd(&out[r0 * HID + col], oacc[mf][nf][0]);
            atomicAdd(&out[r0 * HID + col + 1], oacc[mf][nf][1]);
            atomicAdd(&out[(r0 + 8) * HID + col], oacc[mf][nf][2]);
            atomicAdd(&out[(r0 + 8) * HID + col + 1], oacc[mf][nf][3]);
        }
}

// ---------------------------------------------------------------------------
__global__ void k_norm_A(float* __restrict__ A) {
    long i = (long)blockIdx.x * blockDim.x + threadIdx.x;
    const long total = (long)NN * NN / 4;
    if (i < total) {
        int r = (int)(i >> 11);
        float inv = 1.0f / (g_rowsum[r] + 1e-6f);
        float4 v = ((float4*)A)[i];
        v.x *= inv; v.y *= inv; v.z *= inv; v.w *= inv;
        ((float4*)A)[i] = v;
    }
}

__global__ void k_norm_out(float* __restrict__ o) {
    int i = blockIdx.x * blockDim.x + threadIdx.x;
    if (i < NN * HID) {
        int r = i >> 7;
        o[i] *= 1.0f / (g_rowsum[r] + 1e-6f);
    }
}

// ---------------------------------------------------------------------------
extern "C" void kernel_launch(void* const* d_in, const int* in_sizes, int n_in,
                              void* d_out, int out_size) {
    const float* X = (const float*)d_in[0];
    const float* W = (const float*)d_in[1];
    float* out = (float*)d_out;
    float* A = out + NN * HID;

    k_zero<<<(NN * HID + 255) / 256, 256>>>(out);
    k_gemm_z<<<dim3(NN / 64, HID / 64), 256>>>(X, W);

    cudaFuncSetAttribute(k_pass2, cudaFuncAttributeMaxDynamicSharedMemorySize,
                         SMEM_BYTES);
    k_pass2<<<dim3(2, NN / 128), 256, SMEM_BYTES>>>(A, out);

    k_norm_A<<<(int)(((long)NN * NN / 4 + 255) / 256), 256>>>(A);
    k_norm_out<<<(NN * HID + 255) / 256, 256>>>(out);
}

// round 6
// speedup vs baseline: 4.1427x; 1.2183x over previous
#include <cuda_runtime.h>
#include <cuda_bf16.h>
#include <cstdint>

#define NN 8192
#define IN_DIM 256
#define HID 128
#define PZ 136  // pitch for 128-col tiles (17 x 16B, odd -> ldmatrix conflict-free)
#define PT 72   // pitch for 64-col tiles (9 x 16B, odd)

// smem element offsets (bf16)
#define ZNH_E 0
#define ZNL_E (128 * PZ)
#define ZT_E(buf, hl) (2 * 128 * PZ + ((buf) * 2 + (hl)) * 128 * PT)
#define SHI_E (2 * 128 * PZ + 4 * 128 * PT)
#define SLO_E (SHI_E + 128 * PT)
#define SMEM_BYTES ((SLO_E + 128 * PT) * 2)  // 180224

// ---------------- device scratch (no cudaMalloc allowed) -------------------
__device__ __nv_bfloat16 g_Zhi[NN * HID];
__device__ __nv_bfloat16 g_Zlo[NN * HID];
__device__ __nv_bfloat16 g_ZThi[(long)HID * NN];
__device__ __nv_bfloat16 g_ZTlo[(long)HID * NN];
__device__ float g_outp[2 * NN * HID];  // per-column-half partial out
__device__ float g_rs[2 * NN];          // per-column-half partial rowsum

// ---------------- primitives (baseline PTX, no sm_103a gating) -------------
__device__ __forceinline__ uint32_t smem_u32(const void* p) {
    uint32_t a;
    asm("{ .reg .u64 t; cvta.to.shared.u64 t, %1; cvt.u32.u64 %0, t; }"
        : "=r"(a) : "l"(p));
    return a;
}
__device__ __forceinline__ void ldsm_x4(uint32_t* r, uint32_t addr) {
    asm volatile("ldmatrix.sync.aligned.m8n8.x4.shared.b16 {%0,%1,%2,%3}, [%4];"
                 : "=r"(r[0]), "=r"(r[1]), "=r"(r[2]), "=r"(r[3]) : "r"(addr));
}
__device__ __forceinline__ void ldsm_x2t(uint32_t* r, uint32_t addr) {
    asm volatile("ldmatrix.sync.aligned.m8n8.x2.trans.shared.b16 {%0,%1}, [%2];"
                 : "=r"(r[0]), "=r"(r[1]) : "r"(addr));
}
__device__ __forceinline__ void ldsm_x2(uint32_t* r, uint32_t addr) {
    asm volatile("ldmatrix.sync.aligned.m8n8.x2.shared.b16 {%0,%1}, [%2];"
                 : "=r"(r[0]), "=r"(r[1]) : "r"(addr));
}
__device__ __forceinline__ void mma16816(float* c, const uint32_t* a,
                                         const uint32_t* b) {
    asm volatile(
        "mma.sync.aligned.m16n8k16.row.col.f32.bf16.bf16.f32 "
        "{%0,%1,%2,%3}, {%4,%5,%6,%7}, {%8,%9}, {%0,%1,%2,%3};"
        : "+f"(c[0]), "+f"(c[1]), "+f"(c[2]), "+f"(c[3])
        : "r"(a[0]), "r"(a[1]), "r"(a[2]), "r"(a[3]), "r"(b[0]), "r"(b[1]));
}
__device__ __forceinline__ void cp16(uint32_t dst, const void* src) {
    asm volatile("cp.async.cg.shared.global [%0], [%1], 16;"
                 :: "r"(dst), "l"(src));
}
#define CP_COMMIT() asm volatile("cp.async.commit_group;")
#define CP_WAIT1() asm volatile("cp.async.wait_group 1;")
#define CP_WAIT0() asm volatile("cp.async.wait_group 0;")
__device__ __forceinline__ void stcs2(float* p, float x, float y) {
    asm volatile("st.global.cs.v2.f32 [%0], {%1,%2};" :: "l"(p), "f"(x), "f"(y));
}
__device__ __forceinline__ uint32_t pack_bf2(float x, float y) {
    __nv_bfloat162 t;
    t.x = __float2bfloat16(x);
    t.y = __float2bfloat16(y);
    return *reinterpret_cast<uint32_t*>(&t);
}

// ---------------------------------------------------------------------------
// Phase 1: Z = X @ W^T (fp32), emit bf16 hi/lo + transposed hi/lo
// ---------------------------------------------------------------------------
__global__ __launch_bounds__(256) void k_gemm_z(const float* __restrict__ X,
                                                const float* __restrict__ W) {
    __shared__ float Xs[64][33];
    __shared__ float Ws[64][33];
    const int tid = threadIdx.x;
    const int tx = tid & 15, ty = tid >> 4;
    const int row0 = blockIdx.x * 64;
    const int col0 = blockIdx.y * 64;
    float acc[4][4] = {};

    for (int k0 = 0; k0 < IN_DIM; k0 += 32) {
        for (int idx = tid; idx < 64 * 32; idx += 256) {
            int r = idx >> 5, c = idx & 31;
            Xs[r][c] = X[(row0 + r) * IN_DIM + k0 + c];
            Ws[r][c] = W[(col0 + r) * IN_DIM + k0 + c];
        }
        __syncthreads();
#pragma unroll 8
        for (int k = 0; k < 32; k++) {
            float a[4], b[4];
#pragma unroll
            for (int i = 0; i < 4; i++) a[i] = Xs[ty * 4 + i][k];
#pragma unroll
            for (int j = 0; j < 4; j++) b[j] = Ws[tx * 4 + j][k];
#pragma unroll
            for (int i = 0; i < 4; i++)
#pragma unroll
                for (int j = 0; j < 4; j++) acc[i][j] = fmaf(a[i], b[j], acc[i][j]);
        }
        __syncthreads();
    }
#pragma unroll
    for (int i = 0; i < 4; i++)
#pragma unroll
        for (int j = 0; j < 4; j++) {
            int r = row0 + ty * 4 + i, c = col0 + tx * 4 + j;
            float v = acc[i][j];
            __nv_bfloat16 h = __float2bfloat16(v);
            __nv_bfloat16 l = __float2bfloat16(v - __bfloat162float(h));
            g_Zhi[r * HID + c] = h;
            g_Zlo[r * HID + c] = l;
            g_ZThi[(long)c * NN + r] = h;
            g_ZTlo[(long)c * NN + r] = l;
        }
}

// ---------------------------------------------------------------------------
// copy 128x128 bf16 tile -> smem (pitch PZ), plain loads (once per CTA)
// ---------------------------------------------------------------------------
__device__ __forceinline__ void copy_tile_z(__nv_bfloat16* __restrict__ dst,
                                            const __nv_bfloat16* __restrict__ src,
                                            int tid) {
#pragma unroll
    for (int i = 0; i < 8; i++) {
        int idx = tid + i * 256;
        int row = idx >> 4;
        int c8 = (idx & 15) * 8;
        *(uint4*)&dst[row * PZ + c8] = *(const uint4*)&src[(long)row * HID + c8];
    }
}

// issue async copy of one 128x64 Zt tile pair (hi+lo) into buffer buf
__device__ __forceinline__ void issue_zt(uint32_t smb, int buf, int m0, int tid) {
    const __nv_bfloat16* gh = g_ZThi + m0;
    const __nv_bfloat16* gl = g_ZTlo + m0;
    const uint32_t dH = smb + ZT_E(buf, 0) * 2;
    const uint32_t dL = smb + ZT_E(buf, 1) * 2;
#pragma unroll
    for (int i = 0; i < 4; i++) {
        int idx = tid + i * 256;   // 0..1023
        int row = idx >> 3;        // 0..127 (h)
        int c8 = (idx & 7) * 8;    // 0..56 (m)
        uint32_t so = (uint32_t)(row * PT + c8) * 2;
        long go = (long)row * NN + c8;
        cp16(dH + so, gh + go);
        cp16(dL + so, gl + go);
    }
}

// ---------------------------------------------------------------------------
// Phase 2 (HMMA): CTA = 128-row block x half columns; 64 m-tiles of 64.
// cp.async double-buffered Zt tiles; GEMM1 split-bf16 x3 -> relu -> A(.cs),
// rowsum, S->smem hi/lo; GEMM2 split-bf16 x3 accumulates out partial in regs.
// ---------------------------------------------------------------------------
__global__ __launch_bounds__(256, 1) void k_pass2(float* __restrict__ A) {
    extern __shared__ __nv_bfloat16 sm[];
    __shared__ float red[128];
    const uint32_t smb = smem_u32(sm);
    const int tid = threadIdx.x;
    const int wid = tid >> 5, lane = tid & 31;
    const int wm = wid & 1, wn = wid >> 1;
    const int g = lane >> 2, tq = lane & 3;
    const int l15 = lane & 15;
    const int n0 = blockIdx.y * 128;
    const int cs = blockIdx.x;

    copy_tile_z(sm + ZNH_E, g_Zhi + (long)n0 * HID, tid);
    copy_tile_z(sm + ZNL_E, g_Zlo + (long)n0 * HID, tid);

    // fragment base addresses (bytes)
    const int aRow = wm * 64 + l15;
    const int aCol = (lane >> 4) * 8;
    const uint32_t a1H = smb + (ZNH_E + aRow * PZ + aCol) * 2;
    const uint32_t a1L = smb + (ZNL_E + aRow * PZ + aCol) * 2;
    const uint32_t aSH = smb + (SHI_E + aRow * PT + aCol) * 2;
    const uint32_t aSL = smb + (SLO_E + aRow * PT + aCol) * 2;
    const int b2row = wn * 32 + (lane & 7);
    const int b2off = ((lane >> 3) & 1) * 8;

    float oacc[4][4][4] = {};
    float rs[4][2] = {};

    issue_zt(smb, 0, cs * 4096, tid);
    CP_COMMIT();

    for (int t = 0; t < 64; t++) {
        const int cur = t & 1;
        const int m0 = cs * 4096 + t * 64;
        if (t < 63) {
            issue_zt(smb, cur ^ 1, m0 + 64, tid);
            CP_COMMIT();
            CP_WAIT1();
        } else {
            CP_WAIT0();
        }
        __syncthreads();

        const uint32_t ztH = ZT_E(cur, 0), ztL = ZT_E(cur, 1);
        const uint32_t b1H = smb + (ztH + l15 * PT + wn * 16) * 2;
        const uint32_t b1L = smb + (ztL + l15 * PT + wn * 16) * 2;
        const uint32_t b2H = smb + (ztH + b2row * PT + b2off) * 2;
        const uint32_t b2L = smb + (ztL + b2row * PT + b2off) * 2;

        // ---- GEMM1: S(128x64) = Zn(split) @ Zt(split), warp tile 64x16 ----
        float cacc[4][2][4] = {};
#pragma unroll
        for (int p = 0; p < 3; p++) {
            const uint32_t aB = (p == 2) ? a1L : a1H;
            const uint32_t bB = (p == 1) ? b1L : b1H;
#pragma unroll
            for (int k8 = 0; k8 < 8; k8++) {
                const int k0 = k8 * 16;
                uint32_t a[4][4];
#pragma unroll
                for (int mf = 0; mf < 4; mf++)
                    ldsm_x4(a[mf], aB + (mf * 16 * PZ + k0) * 2);
#pragma unroll
                for (int nf = 0; nf < 2; nf++) {
                    uint32_t b[2];
                    ldsm_x2t(b, bB + (k0 * PT + nf * 8) * 2);
#pragma unroll
                    for (int mf = 0; mf < 4; mf++)
                        mma16816(cacc[mf][nf], a[mf], b);
                }
            }
        }

        // ---- epilogue: relu, rowsum, streaming A store, S->smem hi/lo ----
#pragma unroll
        for (int mf = 0; mf < 4; mf++) {
#pragma unroll
            for (int nf = 0; nf < 2; nf++) {
                float* c = cacc[mf][nf];
                float v0 = fmaxf(c[0], 0.f), v1 = fmaxf(c[1], 0.f);
                float v2 = fmaxf(c[2], 0.f), v3 = fmaxf(c[3], 0.f);
                rs[mf][0] += v0 + v1;
                rs[mf][1] += v2 + v3;
                const int lr = wm * 64 + mf * 16 + g;
                const int lc = wn * 16 + nf * 8 + 2 * tq;
                stcs2(&A[(long)(n0 + lr) * NN + m0 + lc], v0, v1);
                stcs2(&A[(long)(n0 + lr + 8) * NN + m0 + lc], v2, v3);
                float h0 = __bfloat162float(__float2bfloat16(v0));
                float h1 = __bfloat162float(__float2bfloat16(v1));
                float h2 = __bfloat162float(__float2bfloat16(v2));
                float h3 = __bfloat162float(__float2bfloat16(v3));
                *(uint32_t*)&sm[SHI_E + lr * PT + lc] = pack_bf2(v0, v1);
                *(uint32_t*)&sm[SLO_E + lr * PT + lc] = pack_bf2(v0 - h0, v1 - h1);
                *(uint32_t*)&sm[SHI_E + (lr + 8) * PT + lc] = pack_bf2(v2, v3);
                *(uint32_t*)&sm[SLO_E + (lr + 8) * PT + lc] = pack_bf2(v2 - h2, v3 - h3);
            }
        }
        __syncthreads();

        // ---- GEMM2: out(128x128) += S(split) @ Zt-as-B(split), 64x32 ----
#pragma unroll
        for (int p = 0; p < 3; p++) {
            const uint32_t aB = (p == 2) ? aSL : aSH;
            const uint32_t bB = (p == 1) ? b2L : b2H;
#pragma unroll
            for (int k8 = 0; k8 < 4; k8++) {
                const int k0 = k8 * 16;
                uint32_t a[4][4];
#pragma unroll
                for (int mf = 0; mf < 4; mf++)
                    ldsm_x4(a[mf], aB + (mf * 16 * PT + k0) * 2);
#pragma unroll
                for (int nf = 0; nf < 4; nf++) {
                    uint32_t b[2];
                    ldsm_x2(b, bB + (nf * 8 * PT + k0) * 2);
#pragma unroll
                    for (int mf = 0; mf < 4; mf++)
                        mma16816(oacc[mf][nf], a[mf], b);
                }
            }
        }
        __syncthreads();  // all warps done with Zt[cur] + S before reuse
    }

    // ---- rowsum: quad shuffle -> smem -> partial buffer (no atomics) ----
    if (tid < 128) red[tid] = 0.0f;
    __syncthreads();
#pragma unroll
    for (int mf = 0; mf < 4; mf++)
#pragma unroll
        for (int h = 0; h < 2; h++) {
            float v = rs[mf][h];
            v += __shfl_xor_sync(0xFFFFFFFFu, v, 1);
            v += __shfl_xor_sync(0xFFFFFFFFu, v, 2);
            if (tq == 0) atomicAdd(&red[wm * 64 + mf * 16 + g + 8 * h], v);
        }
    __syncthreads();
    if (tid < 128) g_rs[cs * NN + n0 + tid] = red[tid];

    // ---- out partial: direct stores ----
    float* op = g_outp + (long)cs * NN * HID;
#pragma unroll
    for (int mf = 0; mf < 4; mf++)
#pragma unroll
        for (int nf = 0; nf < 4; nf++) {
            const int r0 = n0 + wm * 64 + mf * 16 + g;
            const int col = wn * 32 + nf * 8 + 2 * tq;
            *(float2*)&op[r0 * HID + col] = make_float2(oacc[mf][nf][0], oacc[mf][nf][1]);
            *(float2*)&op[(r0 + 8) * HID + col] = make_float2(oacc[mf][nf][2], oacc[mf][nf][3]);
        }
}

// ---------------------------------------------------------------------------
// Phase 3a: A *= 1/(rowsum+1e-6); streaming, 4 independent float4 per thread
// ---------------------------------------------------------------------------
__global__ __launch_bounds__(256) void k_norm_A(float* __restrict__ A) {
    const long i0 = (long)blockIdx.x * 1024 + threadIdx.x;
    float4 v[4];
    float inv[4];
#pragma unroll
    for (int j = 0; j < 4; j++) {
        long i = i0 + j * 256;
        v[j] = __ldcs(&((const float4*)A)[i]);
        int r = (int)(i >> 11);
        inv[j] = 1.0f / (g_rs[r] + g_rs[NN + r] + 1e-6f);
    }
#pragma unroll
    for (int j = 0; j < 4; j++) {
        long i = i0 + j * 256;
        float4 w = v[j];
        w.x *= inv[j]; w.y *= inv[j]; w.z *= inv[j]; w.w *= inv[j];
        __stcs(&((float4*)A)[i], w);
    }
}

// ---------------------------------------------------------------------------
// Phase 3b: out = (partial0 + partial1) * inv(rowsum)
// ---------------------------------------------------------------------------
__global__ void k_norm_out(float* __restrict__ o) {
    int i = blockIdx.x * blockDim.x + threadIdx.x;
    if (i < NN * HID) {
        int r = i >> 7;
        float inv = 1.0f / (g_rs[r] + g_rs[NN + r] + 1e-6f);
        o[i] = (g_outp[i] + g_outp[NN * HID + i]) * inv;
    }
}

// ---------------------------------------------------------------------------
extern "C" void kernel_launch(void* const* d_in, const int* in_sizes, int n_in,
                              void* d_out, int out_size) {
    const float* X = (const float*)d_in[0];
    const float* W = (const float*)d_in[1];
    float* out = (float*)d_out;
    float* A = out + NN * HID;

    k_gemm_z<<<dim3(NN / 64, HID / 64), 256>>>(X, W);

    cudaFuncSetAttribute(k_pass2, cudaFuncAttributeMaxDynamicSharedMemorySize,
                         SMEM_BYTES);
    k_pass2<<<dim3(2, NN / 128), 256, SMEM_BYTES>>>(A);

    k_norm_A<<<16384, 256>>>(A);
    k_norm_out<<<(NN * HID + 255) / 256, 256>>>(out);
}

// round 7
// speedup vs baseline: 4.5869x; 1.1072x over previous
#include <cuda_runtime.h>
#include <cuda_bf16.h>
#include <cstdint>

#define NN 8192
#define IN_DIM 256
#define HID 128
#define PZ 136  // pitch for 128-col tiles (17 x 16B, odd -> ldmatrix conflict-free)
#define PT 72   // pitch for 64-col tiles (9 x 16B, odd)

// smem element offsets (bf16)
#define ZNH_E 0
#define ZNL_E (128 * PZ)
#define ZT_E(buf, hl) (2 * 128 * PZ + ((buf) * 2 + (hl)) * 128 * PT)
#define SHI_E (2 * 128 * PZ + 4 * 128 * PT)
#define SLO_E (SHI_E + 128 * PT)
#define SMEM_BYTES ((SLO_E + 128 * PT) * 2)  // 180224

// ---------------- device scratch (no cudaMalloc allowed) -------------------
__device__ __nv_bfloat16 g_Zhi[NN * HID];
__device__ __nv_bfloat16 g_Zlo[NN * HID];
__device__ __nv_bfloat16 g_ZThi[(long)HID * NN];
__device__ __nv_bfloat16 g_ZTlo[(long)HID * NN];
__device__ float g_outp[2 * NN * HID];  // per-column-half partial out
__device__ float g_rs[2 * NN];          // per-column-half partial rowsum

// ---------------- primitives (baseline PTX, no sm_103a gating) -------------
__device__ __forceinline__ uint32_t smem_u32(const void* p) {
    uint32_t a;
    asm("{ .reg .u64 t; cvta.to.shared.u64 t, %1; cvt.u32.u64 %0, t; }"
        : "=r"(a) : "l"(p));
    return a;
}
__device__ __forceinline__ void ldsm_x4(uint32_t* r, uint32_t addr) {
    asm volatile("ldmatrix.sync.aligned.m8n8.x4.shared.b16 {%0,%1,%2,%3}, [%4];"
                 : "=r"(r[0]), "=r"(r[1]), "=r"(r[2]), "=r"(r[3]) : "r"(addr));
}
__device__ __forceinline__ void ldsm_x4t(uint32_t* r, uint32_t addr) {
    asm volatile("ldmatrix.sync.aligned.m8n8.x4.trans.shared.b16 {%0,%1,%2,%3}, [%4];"
                 : "=r"(r[0]), "=r"(r[1]), "=r"(r[2]), "=r"(r[3]) : "r"(addr));
}
__device__ __forceinline__ void mma16816(float* c, const uint32_t* a,
                                         const uint32_t* b) {
    asm volatile(
        "mma.sync.aligned.m16n8k16.row.col.f32.bf16.bf16.f32 "
        "{%0,%1,%2,%3}, {%4,%5,%6,%7}, {%8,%9}, {%0,%1,%2,%3};"
        : "+f"(c[0]), "+f"(c[1]), "+f"(c[2]), "+f"(c[3])
        : "r"(a[0]), "r"(a[1]), "r"(a[2]), "r"(a[3]), "r"(b[0]), "r"(b[1]));
}
__device__ __forceinline__ void cp16(uint32_t dst, const void* src) {
    asm volatile("cp.async.cg.shared.global [%0], [%1], 16;"
                 :: "r"(dst), "l"(src));
}
#define CP_COMMIT() asm volatile("cp.async.commit_group;")
#define CP_WAIT1() asm volatile("cp.async.wait_group 1;")
#define CP_WAIT0() asm volatile("cp.async.wait_group 0;")
__device__ __forceinline__ void stcs2(float* p, float x, float y) {
    asm volatile("st.global.cs.v2.f32 [%0], {%1,%2};" :: "l"(p), "f"(x), "f"(y));
}
__device__ __forceinline__ uint32_t pack_bf2(float x, float y) {
    __nv_bfloat162 t;
    t.x = __float2bfloat16(x);
    t.y = __float2bfloat16(y);
    return *reinterpret_cast<uint32_t*>(&t);
}

// ---------------------------------------------------------------------------
// Phase 1: Z = X @ W^T (fp32), emit bf16 hi/lo + smem-staged transposed hi/lo
// ---------------------------------------------------------------------------
__global__ __launch_bounds__(256) void k_gemm_z(const float* __restrict__ X,
                                                const float* __restrict__ W) {
    __shared__ __align__(16) float pool[2 * 64 * 33];  // Xs | Ws, reused for transpose
    float* Xs = pool;
    float* Ws = pool + 64 * 33;
    const int tid = threadIdx.x;
    const int tx = tid & 15, ty = tid >> 4;
    const int row0 = blockIdx.x * 64;
    const int col0 = blockIdx.y * 64;
    float acc[4][4] = {};

    for (int k0 = 0; k0 < IN_DIM; k0 += 32) {
        for (int idx = tid; idx < 64 * 32; idx += 256) {
            int r = idx >> 5, c = idx & 31;
            Xs[r * 33 + c] = X[(row0 + r) * IN_DIM + k0 + c];
            Ws[r * 33 + c] = W[(col0 + r) * IN_DIM + k0 + c];
        }
        __syncthreads();
#pragma unroll 8
        for (int k = 0; k < 32; k++) {
            float a[4], b[4];
#pragma unroll
            for (int i = 0; i < 4; i++) a[i] = Xs[(ty * 4 + i) * 33 + k];
#pragma unroll
            for (int j = 0; j < 4; j++) b[j] = Ws[(tx * 4 + j) * 33 + k];
#pragma unroll
            for (int i = 0; i < 4; i++)
#pragma unroll
                for (int j = 0; j < 4; j++) acc[i][j] = fmaf(a[i], b[j], acc[i][j]);
        }
        __syncthreads();
    }

    // split into hi/lo; direct row-major stores (coalesced)
    __nv_bfloat16 h4[4][4], l4[4][4];
#pragma unroll
    for (int i = 0; i < 4; i++)
#pragma unroll
        for (int j = 0; j < 4; j++) {
            int r = row0 + ty * 4 + i, c = col0 + tx * 4 + j;
            float v = acc[i][j];
            __nv_bfloat16 h = __float2bfloat16(v);
            __nv_bfloat16 l = __float2bfloat16(v - __bfloat162float(h));
            h4[i][j] = h; l4[i][j] = l;
            g_Zhi[r * HID + c] = h;
            g_Zlo[r * HID + c] = l;
        }

    // transposed stores staged through smem (coalesced uint4 out)
    __nv_bfloat16* tb = (__nv_bfloat16*)pool;  // 64 x 72 bf16 = 9216B
#pragma unroll
    for (int pass = 0; pass < 2; pass++) {
        __syncthreads();
#pragma unroll
        for (int i = 0; i < 4; i++)
#pragma unroll
            for (int j = 0; j < 4; j++)
                tb[(tx * 4 + j) * 72 + ty * 4 + i] = pass ? l4[i][j] : h4[i][j];
        __syncthreads();
        __nv_bfloat16* gp = pass ? g_ZTlo : g_ZThi;
#pragma unroll
        for (int k = 0; k < 2; k++) {
            int idx = tid + k * 256;
            int c_loc = idx >> 3;
            int r8 = (idx & 7) * 8;
            *(uint4*)&gp[(long)(col0 + c_loc) * NN + row0 + r8] =
                *(uint4*)&tb[c_loc * 72 + r8];
        }
    }
}

// ---------------------------------------------------------------------------
// copy 128x128 bf16 tile -> smem (pitch PZ), plain loads (once per CTA)
// ---------------------------------------------------------------------------
__device__ __forceinline__ void copy_tile_z(__nv_bfloat16* __restrict__ dst,
                                            const __nv_bfloat16* __restrict__ src,
                                            int tid) {
#pragma unroll
    for (int i = 0; i < 8; i++) {
        int idx = tid + i * 256;
        int row = idx >> 4;
        int c8 = (idx & 15) * 8;
        *(uint4*)&dst[row * PZ + c8] = *(const uint4*)&src[(long)row * HID + c8];
    }
}

// issue async copy of one 128x64 Zt tile pair (hi+lo) into buffer buf
__device__ __forceinline__ void issue_zt(uint32_t smb, int buf, int m0, int tid) {
    const __nv_bfloat16* gh = g_ZThi + m0;
    const __nv_bfloat16* gl = g_ZTlo + m0;
    const uint32_t dH = smb + ZT_E(buf, 0) * 2;
    const uint32_t dL = smb + ZT_E(buf, 1) * 2;
#pragma unroll
    for (int i = 0; i < 4; i++) {
        int idx = tid + i * 256;   // 0..1023
        int row = idx >> 3;        // 0..127 (h)
        int c8 = (idx & 7) * 8;    // 0..56 (m)
        uint32_t so = (uint32_t)(row * PT + c8) * 2;
        long go = (long)row * NN + c8;
        cp16(dH + so, gh + go);
        cp16(dL + so, gl + go);
    }
}

// ---------------------------------------------------------------------------
// Phase 2 (HMMA): CTA = 128-row block x half columns; 64 m-tiles of 64.
// cp.async double-buffered Zt; frag-cached 3-pass split-bf16 GEMMs.
// GEMM1 warps (4m,2n) 32x32; GEMM2 warps (2m,4n) 64x32.
// ---------------------------------------------------------------------------
__global__ __launch_bounds__(256, 1) void k_pass2(float* __restrict__ A) {
    extern __shared__ __nv_bfloat16 sm[];
    __shared__ float red[128];
    const uint32_t smb = smem_u32(sm);
    const int tid = threadIdx.x;
    const int wid = tid >> 5, lane = tid & 31;
    const int wm = wid & 1, wn = wid >> 1;      // GEMM2 layout (2m,4n)
    const int wm4 = wid & 3, wn2 = wid >> 2;    // GEMM1 layout (4m,2n)
    const int g = lane >> 2, tq = lane & 3;
    const int l15 = lane & 15;
    const int hi8 = (lane >> 4) * 8;
    const int n0 = blockIdx.y * 128;
    const int cs = blockIdx.x;

    copy_tile_z(sm + ZNH_E, g_Zhi + (long)n0 * HID, tid);
    copy_tile_z(sm + ZNL_E, g_Zlo + (long)n0 * HID, tid);

    // GEMM1 A frags: rows wm4*32 + l15 (+16 per mf), col hi8 (+k0)
    const uint32_t a1H = smb + (ZNH_E + (wm4 * 32 + l15) * PZ + hi8) * 2;
    const uint32_t a1L = smb + (ZNL_E + (wm4 * 32 + l15) * PZ + hi8) * 2;
    // GEMM2 A frags (S): rows wm*64 + l15 (+16 per mf)
    const uint32_t aSH = smb + (SHI_E + (wm * 64 + l15) * PT + hi8) * 2;
    const uint32_t aSL = smb + (SLO_E + (wm * 64 + l15) * PT + hi8) * 2;
    // GEMM2 B rows (n=h): wn*32 + pair*16 + hi8' + (lane&7), col (lane>>3 &1)*8
    const int b2row = wn * 32 + ((lane >> 4) & 1) * 8 + (lane & 7);
    const int b2off = ((lane >> 3) & 1) * 8;

    float oacc[4][4][4] = {};
    float rs[2][2] = {};

    issue_zt(smb, 0, cs * 4096, tid);
    CP_COMMIT();

    for (int t = 0; t < 64; t++) {
        const int cur = t & 1;
        const int m0 = cs * 4096 + t * 64;
        if (t < 63) {
            issue_zt(smb, cur ^ 1, m0 + 64, tid);
            CP_COMMIT();
            CP_WAIT1();
        } else {
            CP_WAIT0();
        }
        __syncthreads();

        const uint32_t ztH = ZT_E(cur, 0), ztL = ZT_E(cur, 1);
        // GEMM1 B (trans): rows k (h) = l15, col wn2*32 + pair*16 + hi8
        const uint32_t b1H = smb + (ztH + l15 * PT + wn2 * 32 + hi8) * 2;
        const uint32_t b1L = smb + (ztL + l15 * PT + wn2 * 32 + hi8) * 2;
        const uint32_t b2H = smb + (ztH + b2row * PT + b2off) * 2;
        const uint32_t b2L = smb + (ztL + b2row * PT + b2off) * 2;

        // ---- GEMM1: S(128x64) = Zn(split) @ Zt(split); warp 32x32 ----
        float cacc[2][4][4] = {};
#pragma unroll
        for (int k8 = 0; k8 < 8; k8++) {
            const int k0 = k8 * 16;
            uint32_t aH[2][4], aL[2][4], bH[2][4], bL[2][4];
#pragma unroll
            for (int mf = 0; mf < 2; mf++) {
                ldsm_x4(aH[mf], a1H + (mf * 16 * PZ + k0) * 2);
                ldsm_x4(aL[mf], a1L + (mf * 16 * PZ + k0) * 2);
            }
#pragma unroll
            for (int pr = 0; pr < 2; pr++) {
                ldsm_x4t(bH[pr], b1H + (k0 * PT + pr * 16) * 2);
                ldsm_x4t(bL[pr], b1L + (k0 * PT + pr * 16) * 2);
            }
#pragma unroll
            for (int mf = 0; mf < 2; mf++)
#pragma unroll
                for (int pr = 0; pr < 2; pr++) {
                    mma16816(cacc[mf][2 * pr], aH[mf], &bH[pr][0]);
                    mma16816(cacc[mf][2 * pr + 1], aH[mf], &bH[pr][2]);
                    mma16816(cacc[mf][2 * pr], aH[mf], &bL[pr][0]);
                    mma16816(cacc[mf][2 * pr + 1], aH[mf], &bL[pr][2]);
                    mma16816(cacc[mf][2 * pr], aL[mf], &bH[pr][0]);
                    mma16816(cacc[mf][2 * pr + 1], aL[mf], &bH[pr][2]);
                }
        }

        // ---- epilogue: relu, rowsum, streaming A store, S->smem hi/lo ----
#pragma unroll
        for (int mf = 0; mf < 2; mf++) {
#pragma unroll
            for (int nf = 0; nf < 4; nf++) {
                float* c = cacc[mf][nf];
                float v0 = fmaxf(c[0], 0.f), v1 = fmaxf(c[1], 0.f);
                float v2 = fmaxf(c[2], 0.f), v3 = fmaxf(c[3], 0.f);
                rs[mf][0] += v0 + v1;
                rs[mf][1] += v2 + v3;
                const int lr = wm4 * 32 + mf * 16 + g;
                const int lc = wn2 * 32 + nf * 8 + 2 * tq;
                stcs2(&A[(long)(n0 + lr) * NN + m0 + lc], v0, v1);
                stcs2(&A[(long)(n0 + lr + 8) * NN + m0 + lc], v2, v3);
                float h0 = __bfloat162float(__float2bfloat16(v0));
                float h1 = __bfloat162float(__float2bfloat16(v1));
                float h2 = __bfloat162float(__float2bfloat16(v2));
                float h3 = __bfloat162float(__float2bfloat16(v3));
                *(uint32_t*)&sm[SHI_E + lr * PT + lc] = pack_bf2(v0, v1);
                *(uint32_t*)&sm[SLO_E + lr * PT + lc] = pack_bf2(v0 - h0, v1 - h1);
                *(uint32_t*)&sm[SHI_E + (lr + 8) * PT + lc] = pack_bf2(v2, v3);
                *(uint32_t*)&sm[SLO_E + (lr + 8) * PT + lc] = pack_bf2(v2 - h2, v3 - h3);
            }
        }
        __syncthreads();

        // ---- GEMM2: out(128x128) += S(split) @ Zt-as-B(split); warp 64x32 ----
#pragma unroll
        for (int k8 = 0; k8 < 4; k8++) {
            const int k0 = k8 * 16;
            uint32_t aH[4][4], aL[4][4], bH[2][4], bL[2][4];
#pragma unroll
            for (int mf = 0; mf < 4; mf++) {
                ldsm_x4(aH[mf], aSH + (mf * 16 * PT + k0) * 2);
                ldsm_x4(aL[mf], aSL + (mf * 16 * PT + k0) * 2);
            }
#pragma unroll
            for (int pr = 0; pr < 2; pr++) {
                ldsm_x4(bH[pr], b2H + (pr * 16 * PT + k0) * 2);
                ldsm_x4(bL[pr], b2L + (pr * 16 * PT + k0) * 2);
            }
#pragma unroll
            for (int mf = 0; mf < 4; mf++)
#pragma unroll
                for (int pr = 0; pr < 2; pr++) {
                    mma16816(oacc[mf][2 * pr], aH[mf], &bH[pr][0]);
                    mma16816(oacc[mf][2 * pr + 1], aH[mf], &bH[pr][2]);
                    mma16816(oacc[mf][2 * pr], aH[mf], &bL[pr][0]);
                    mma16816(oacc[mf][2 * pr + 1], aH[mf], &bL[pr][2]);
                    mma16816(oacc[mf][2 * pr], aL[mf], &bH[pr][0]);
                    mma16816(oacc[mf][2 * pr + 1], aL[mf], &bH[pr][2]);
                }
        }
        __syncthreads();  // all warps done with Zt[cur] + S before reuse
    }

    // ---- rowsum: quad shuffle -> smem -> partial buffer (no atomics) ----
    if (tid < 128) red[tid] = 0.0f;
    __syncthreads();
#pragma unroll
    for (int mf = 0; mf < 2; mf++)
#pragma unroll
        for (int h = 0; h < 2; h++) {
            float v = rs[mf][h];
            v += __shfl_xor_sync(0xFFFFFFFFu, v, 1);
            v += __shfl_xor_sync(0xFFFFFFFFu, v, 2);
            if (tq == 0) atomicAdd(&red[wm4 * 32 + mf * 16 + g + 8 * h], v);
        }
    __syncthreads();
    if (tid < 128) g_rs[cs * NN + n0 + tid] = red[tid];

    // ---- out partial: direct stores ----
    float* op = g_outp + (long)cs * NN * HID;
#pragma unroll
    for (int mf = 0; mf < 4; mf++)
#pragma unroll
        for (int nf = 0; nf < 4; nf++) {
            const int r0 = n0 + wm * 64 + mf * 16 + g;
            const int col = wn * 32 + nf * 8 + 2 * tq;
            *(float2*)&op[r0 * HID + col] = make_float2(oacc[mf][nf][0], oacc[mf][nf][1]);
            *(float2*)&op[(r0 + 8) * HID + col] = make_float2(oacc[mf][nf][2], oacc[mf][nf][3]);
        }
}

// ---------------------------------------------------------------------------
// Phase 3a: A *= 1/(rowsum+1e-6); streaming, 4 independent float4 per thread
// ---------------------------------------------------------------------------
__global__ __launch_bounds__(256) void k_norm_A(float* __restrict__ A) {
    const long i0 = (long)blockIdx.x * 1024 + threadIdx.x;
    float4 v[4];
    float inv[4];
#pragma unroll
    for (int j = 0; j < 4; j++) {
        long i = i0 + j * 256;
        v[j] = __ldcs(&((const float4*)A)[i]);
        int r = (int)(i >> 11);
        inv[j] = 1.0f / (g_rs[r] + g_rs[NN + r] + 1e-6f);
    }
#pragma unroll
    for (int j = 0; j < 4; j++) {
        long i = i0 + j * 256;
        float4 w = v[j];
        w.x *= inv[j]; w.y *= inv[j]; w.z *= inv[j]; w.w *= inv[j];
        __stcs(&((float4*)A)[i], w);
    }
}

// ---------------------------------------------------------------------------
// Phase 3b: out = (partial0 + partial1) * inv(rowsum)
// ---------------------------------------------------------------------------
__global__ void k_norm_out(float* __restrict__ o) {
    int i = blockIdx.x * blockDim.x + threadIdx.x;
    if (i < NN * HID) {
        int r = i >> 7;
        float inv = 1.0f / (g_rs[r] + g_rs[NN + r] + 1e-6f);
        o[i] = (g_outp[i] + g_outp[NN * HID + i]) * inv;
    }
}

// ---------------------------------------------------------------------------
extern "C" void kernel_launch(void* const* d_in, const int* in_sizes, int n_in,
                              void* d_out, int out_size) {
    const float* X = (const float*)d_in[0];
    const float* W = (const float*)d_in[1];
    float* out = (float*)d_out;
    float* A = out + NN * HID;

    k_gemm_z<<<dim3(NN / 64, HID / 64), 256>>>(X, W);

    cudaFuncSetAttribute(k_pass2, cudaFuncAttributeMaxDynamicSharedMemorySize,
                         SMEM_BYTES);
    k_pass2<<<dim3(2, NN / 128), 256, SMEM_BYTES>>>(A);

    k_norm_A<<<16384, 256>>>(A);
    k_norm_out<<<(NN * HID + 255) / 256, 256>>>(out);
}